// round 16
// baseline (speedup 1.0000x reference)
#include <cuda_runtime.h>
#include <cuda_fp16.h>
#include <cstdint>
#include <cstdio>

#define D 64
#define NNODES 16384
#define NE 32768
#define NG 256
#define TPQ 12
#define NT (NG * TPQ)   // 3072

// ---------------- scratch (static device allocations) ----------------
__device__ __half g_ew[(size_t)NE * (D * D)];  // 256 MB (fp16)
__device__ float g_hidden[NE * D];
__device__ float g_x[NNODES * D];              // out == h
__device__ float g_agg[NNODES * D];
__device__ float g_m[NNODES * D];
__device__ float g_deg[NNODES];
__device__ float g_rootT[D * D];
__device__ float g_gru_wihT[64 * 192];
__device__ float g_gru_whhT[64 * 192];
__device__ float g_s2s_wihT[128 * 256];
__device__ float g_s2s_whhT[64 * 256];
__device__ float g_mem_wihT[128 * 256];
__device__ float g_lin1T[320 * 64];
__device__ float g_hx[NG * D];

__device__ __forceinline__ float sigf(float x) { return 1.0f / (1.0f + expf(-x)); }

// ---------------- prologue kernels ----------------
__global__ void k_hidden(const float* __restrict__ ea, const float* __restrict__ w,
                         const float* __restrict__ b, float* __restrict__ out) {
    int i = blockIdx.x * blockDim.x + threadIdx.x;
    if (i >= NE * D) return;
    int e = i >> 6, j = i & 63;
    float v = b[j];
#pragma unroll
    for (int k = 0; k < 6; k++) v += ea[e * 6 + k] * w[j * 6 + k];
    out[i] = fmaxf(v, 0.0f);
}

__global__ void k_lin0z(const float* __restrict__ x, const float* __restrict__ w,
                        const float* __restrict__ b, float* __restrict__ out,
                        float* __restrict__ agg, float* __restrict__ deg) {
    int i = blockIdx.x * blockDim.x + threadIdx.x;
    if (i >= NNODES * D) return;
    int n = i >> 6, o = i & 63;
    float v = b[o] + x[n * 3 + 0] * w[o * 3 + 0] + x[n * 3 + 1] * w[o * 3 + 1] +
              x[n * 3 + 2] * w[o * 3 + 2];
    out[i] = fmaxf(v, 0.0f);
    agg[i] = 0.0f;
    if (o == 0) deg[n] = 0.0f;
}

__global__ void k_transpose(const float* __restrict__ in, float* __restrict__ out, int R, int C) {
    int i = blockIdx.x * blockDim.x + threadIdx.x;
    if (i < R * C) {
        int r = i / C, c = i % C;
        out[c * R + r] = in[i];
    }
}

__global__ void k_prep(const float* __restrict__ gru_wih, const float* __restrict__ gru_whh,
                       const float* __restrict__ s2s_wih, const float* __restrict__ s2s_whh,
                       const float* __restrict__ mem_wih, const float* __restrict__ lin1_w,
                       float* __restrict__ gruWihT, float* __restrict__ gruWhhT,
                       float* __restrict__ s2swihT, float* __restrict__ s2swhhT,
                       float* __restrict__ memwihT, float* __restrict__ lin1T) {
    int i = blockIdx.x * blockDim.x + threadIdx.x;
    if (i < 12288) {
        int r = i / 64, c = i % 64;
        gruWihT[c * 192 + r] = gru_wih[i];
    } else if (i < 24576) {
        int j = i - 12288;
        int r = j / 64, c = j % 64;
        gruWhhT[c * 192 + r] = gru_whh[j];
    } else if (i < 57344) {
        int j = i - 24576;
        int r = j / 128, c = j % 128;
        s2swihT[c * 256 + r] = s2s_wih[j];
    } else if (i < 73728) {
        int j = i - 57344;
        int r = j / 64, c = j % 64;
        s2swhhT[c * 256 + r] = s2s_whh[j];
    } else if (i < 106496) {
        int j = i - 73728;
        int r = j / 128, c = j % 128;
        memwihT[c * 256 + r] = mem_wih[j];
    } else if (i < 126976) {
        int j = i - 106496;
        int r = j / 320, c = j % 320;
        lin1T[c * 64 + r] = lin1_w[j];
    }
}

__global__ void k_deg(const int* __restrict__ eidx, float* __restrict__ deg) {
    int e = blockIdx.x * blockDim.x + threadIdx.x;
    if (e < NE) atomicAdd(&deg[eidx[NE + e]], 1.0f);
}

// ---------------- fp16x2 (Markidis) MMA GEMM -> fp16: ew = hidden @ e2_w^T + b2 -------
// Each fp32 operand split a = hi(fp16) + lo(fp16); C = hi*hi + hi*lo + lo*hi (err ~2^-22,
// below the fp16 C-store rounding). m16n8k16.f16 MMAs: half the instructions and half the
// shared traffic of the 3xTF32 version at identical accuracy.
// 128x64 block tile, K staged 32 at a time. smem 384*17*4 = 26.1 KB. 8 warps (4m x 2n).
__global__ void __launch_bounds__(256, 2) k_ew_fp16x2(
    const float* __restrict__ A, const float* __restrict__ B,
    const float* __restrict__ bias, __half* __restrict__ C) {
    __shared__ __half2 AsH[128 * 17];   // [row][k/2], 16 half2 + 1 pad
    __shared__ __half2 AsL[128 * 17];
    __shared__ __half2 BsH[64 * 17];
    __shared__ __half2 BsL[64 * 17];
    int t = threadIdx.x;
    int m0 = blockIdx.y << 7, n0 = blockIdx.x << 6;
    int lane = t & 31, w = t >> 5;
    int wm = (w >> 1) << 5;   // 0,32,64,96
    int wn = (w & 1) << 5;    // 0,32
    int grp = lane >> 2, tig = lane & 3;
    float acc[2][4][4];
#pragma unroll
    for (int a = 0; a < 2; a++)
#pragma unroll
        for (int b = 0; b < 4; b++)
#pragma unroll
            for (int c = 0; c < 4; c++) acc[a][b][c] = 0.0f;

#pragma unroll
    for (int ks = 0; ks < 2; ks++) {
        int kbase = ks << 5;
        // stage A: 128 rows x 32 cols (4 float4/thread)
#pragma unroll
        for (int i = t; i < 1024; i += 256) {
            int r = i >> 3, c4 = (i & 7) << 2;
            float4 va = *(const float4*)(A + (size_t)(m0 + r) * 64 + kbase + c4);
            __half hx = __float2half_rn(va.x), hy = __float2half_rn(va.y);
            __half hz = __float2half_rn(va.z), hw = __float2half_rn(va.w);
            int idx = r * 17 + (c4 >> 1);
            AsH[idx] = __halves2half2(hx, hy);
            AsH[idx + 1] = __halves2half2(hz, hw);
            AsL[idx] = __halves2half2(__float2half_rn(va.x - __half2float(hx)),
                                      __float2half_rn(va.y - __half2float(hy)));
            AsL[idx + 1] = __halves2half2(__float2half_rn(va.z - __half2float(hz)),
                                          __float2half_rn(va.w - __half2float(hw)));
        }
        // stage B: 64 rows x 32 cols (2 float4/thread)
#pragma unroll
        for (int i = t; i < 512; i += 256) {
            int r = i >> 3, c4 = (i & 7) << 2;
            float4 vb = *(const float4*)(B + (size_t)(n0 + r) * 64 + kbase + c4);
            __half hx = __float2half_rn(vb.x), hy = __float2half_rn(vb.y);
            __half hz = __float2half_rn(vb.z), hw = __float2half_rn(vb.w);
            int idx = r * 17 + (c4 >> 1);
            BsH[idx] = __halves2half2(hx, hy);
            BsH[idx + 1] = __halves2half2(hz, hw);
            BsL[idx] = __halves2half2(__float2half_rn(vb.x - __half2float(hx)),
                                      __float2half_rn(vb.y - __half2float(hy)));
            BsL[idx + 1] = __halves2half2(__float2half_rn(vb.z - __half2float(hz)),
                                          __float2half_rn(vb.w - __half2float(hw)));
        }
        __syncthreads();
#pragma unroll
        for (int k0 = 0; k0 < 32; k0 += 16) {
            int kh = k0 >> 1;   // half2 offset within row: 0 or 8
            uint32_t afh[2][4], afl[2][4];
#pragma unroll
            for (int mt = 0; mt < 2; mt++) {
                int row = wm + (mt << 4) + grp;
                int i0 = row * 17 + kh + tig;
                int i1 = (row + 8) * 17 + kh + tig;
                afh[mt][0] = *(const uint32_t*)&AsH[i0];
                afh[mt][1] = *(const uint32_t*)&AsH[i1];
                afh[mt][2] = *(const uint32_t*)&AsH[i0 + 4];
                afh[mt][3] = *(const uint32_t*)&AsH[i1 + 4];
                afl[mt][0] = *(const uint32_t*)&AsL[i0];
                afl[mt][1] = *(const uint32_t*)&AsL[i1];
                afl[mt][2] = *(const uint32_t*)&AsL[i0 + 4];
                afl[mt][3] = *(const uint32_t*)&AsL[i1 + 4];
            }
#pragma unroll
            for (int nt = 0; nt < 4; nt++) {
                int col = wn + (nt << 3) + grp;
                int j0 = col * 17 + kh + tig;
                uint32_t bh0 = *(const uint32_t*)&BsH[j0];
                uint32_t bh1 = *(const uint32_t*)&BsH[j0 + 4];
                uint32_t bl0 = *(const uint32_t*)&BsL[j0];
                uint32_t bl1 = *(const uint32_t*)&BsL[j0 + 4];
#pragma unroll
                for (int mt = 0; mt < 2; mt++) {
                    // hi * lo
                    asm volatile(
                        "mma.sync.aligned.m16n8k16.row.col.f32.f16.f16.f32 "
                        "{%0,%1,%2,%3}, {%4,%5,%6,%7}, {%8,%9}, {%0,%1,%2,%3};\n"
                        : "+f"(acc[mt][nt][0]), "+f"(acc[mt][nt][1]),
                          "+f"(acc[mt][nt][2]), "+f"(acc[mt][nt][3])
                        : "r"(afh[mt][0]), "r"(afh[mt][1]), "r"(afh[mt][2]), "r"(afh[mt][3]),
                          "r"(bl0), "r"(bl1));
                    // lo * hi
                    asm volatile(
                        "mma.sync.aligned.m16n8k16.row.col.f32.f16.f16.f32 "
                        "{%0,%1,%2,%3}, {%4,%5,%6,%7}, {%8,%9}, {%0,%1,%2,%3};\n"
                        : "+f"(acc[mt][nt][0]), "+f"(acc[mt][nt][1]),
                          "+f"(acc[mt][nt][2]), "+f"(acc[mt][nt][3])
                        : "r"(afl[mt][0]), "r"(afl[mt][1]), "r"(afl[mt][2]), "r"(afl[mt][3]),
                          "r"(bh0), "r"(bh1));
                    // hi * hi
                    asm volatile(
                        "mma.sync.aligned.m16n8k16.row.col.f32.f16.f16.f32 "
                        "{%0,%1,%2,%3}, {%4,%5,%6,%7}, {%8,%9}, {%0,%1,%2,%3};\n"
                        : "+f"(acc[mt][nt][0]), "+f"(acc[mt][nt][1]),
                          "+f"(acc[mt][nt][2]), "+f"(acc[mt][nt][3])
                        : "r"(afh[mt][0]), "r"(afh[mt][1]), "r"(afh[mt][2]), "r"(afh[mt][3]),
                          "r"(bh0), "r"(bh1));
                }
            }
        }
        __syncthreads();
    }
#pragma unroll
    for (int mt = 0; mt < 2; mt++) {
        int row = m0 + wm + (mt << 4) + grp;
#pragma unroll
        for (int nt = 0; nt < 4; nt++) {
            int col = n0 + wn + (nt << 3) + (tig << 1);
            float b0v = bias[col], b1v = bias[col + 1];
            *(__half2*)(C + (size_t)row * 4096 + col) =
                __floats2half2_rn(acc[mt][nt][0] + b0v, acc[mt][nt][1] + b1v);
            *(__half2*)(C + (size_t)(row + 8) * 4096 + col) =
                __floats2half2_rn(acc[mt][nt][2] + b0v, acc[mt][nt][3] + b1v);
        }
    }
}

// ---------------- generic K=64 GEMM (root conv epilogue; zeroes agg after read) -------
__global__ void k_gemm64(const float* __restrict__ A, const float* __restrict__ B,
                         const float* __restrict__ bias, float* __restrict__ C,
                         int Ncols, int epi, float* __restrict__ agg,
                         const float* __restrict__ deg) {
    __shared__ float As[64 * 65];
    __shared__ float Bs[64 * 65];
    int t = threadIdx.x;
    int m0 = blockIdx.y << 6, n0 = blockIdx.x << 6;
    int r = t >> 4, c4 = (t & 15) << 2;
#pragma unroll
    for (int rr = 0; rr < 64; rr += 16) {
        float4 va = *(const float4*)(A + (size_t)(m0 + r + rr) * 64 + c4);
        As[(r + rr) * 65 + c4 + 0] = va.x;
        As[(r + rr) * 65 + c4 + 1] = va.y;
        As[(r + rr) * 65 + c4 + 2] = va.z;
        As[(r + rr) * 65 + c4 + 3] = va.w;
        float4 vb = *(const float4*)(B + (size_t)(n0 + r + rr) * 64 + c4);
        Bs[(r + rr) * 65 + c4 + 0] = vb.x;
        Bs[(r + rr) * 65 + c4 + 1] = vb.y;
        Bs[(r + rr) * 65 + c4 + 2] = vb.z;
        Bs[(r + rr) * 65 + c4 + 3] = vb.w;
    }
    __syncthreads();
    int tn = (t & 15) << 2;
    int tm = (t >> 4) << 2;
    float acc[4][4] = {};
#pragma unroll 8
    for (int k = 0; k < 64; k++) {
        float a0 = As[(tm + 0) * 65 + k];
        float a1 = As[(tm + 1) * 65 + k];
        float a2 = As[(tm + 2) * 65 + k];
        float a3 = As[(tm + 3) * 65 + k];
        float b0 = Bs[(tn + 0) * 65 + k];
        float b1 = Bs[(tn + 1) * 65 + k];
        float b2 = Bs[(tn + 2) * 65 + k];
        float b3 = Bs[(tn + 3) * 65 + k];
        acc[0][0] += a0 * b0; acc[0][1] += a0 * b1; acc[0][2] += a0 * b2; acc[0][3] += a0 * b3;
        acc[1][0] += a1 * b0; acc[1][1] += a1 * b1; acc[1][2] += a1 * b2; acc[1][3] += a1 * b3;
        acc[2][0] += a2 * b0; acc[2][1] += a2 * b1; acc[2][2] += a2 * b2; acc[2][3] += a2 * b3;
        acc[3][0] += a3 * b0; acc[3][1] += a3 * b1; acc[3][2] += a3 * b2; acc[3][3] += a3 * b3;
    }
#pragma unroll
    for (int i = 0; i < 4; i++) {
        int gm = m0 + tm + i;
        float vals[4];
#pragma unroll
        for (int j = 0; j < 4; j++) {
            float v = acc[i][j] + bias[n0 + tn + j];
            if (epi == 1) {
                size_t ai = (size_t)gm * 64 + n0 + tn + j;
                v += agg[ai] * (1.0f / fmaxf(deg[gm], 1.0f));
                agg[ai] = 0.0f;
                v = fmaxf(v, 0.0f);
            }
            vals[j] = v;
        }
        *(float4*)(C + (size_t)gm * Ncols + n0 + tn) =
            make_float4(vals[0], vals[1], vals[2], vals[3]);
    }
}

// ---------------- per-edge einsum + scatter (fp16 ew, streaming loads) ----------------
__global__ void k_msg(const float* __restrict__ x, const int* __restrict__ eidx,
                      const __half* __restrict__ ew, float* __restrict__ agg) {
    int w = threadIdx.x >> 5, lane = threadIdx.x & 31;
    int e = blockIdx.x * 8 + w;
    int src = eidx[e], dst = eidx[NE + e];
    __shared__ float so[8][64];
    so[w][lane] = x[(size_t)src * 64 + lane];
    so[w][lane + 32] = x[(size_t)src * 64 + 32 + lane];
    __syncwarp();
    int half_ = lane >> 4;
    int cq = lane & 15;
    const __half* base = ew + (size_t)e * 4096 + (cq << 2);
    float a0 = 0.0f, a1 = 0.0f, a2 = 0.0f, a3 = 0.0f;
#pragma unroll 16
    for (int j = 0; j < 32; j++) {
        int row = (j << 1) + half_;
        float s = so[w][row];
        uint2 raw = __ldcs((const uint2*)(base + (row << 6)));
        float2 f01 = __half22float2(*reinterpret_cast<__half2*>(&raw.x));
        float2 f23 = __half22float2(*reinterpret_cast<__half2*>(&raw.y));
        a0 += s * f01.x; a1 += s * f01.y; a2 += s * f23.x; a3 += s * f23.y;
    }
    a0 += __shfl_xor_sync(0xffffffffu, a0, 16);
    a1 += __shfl_xor_sync(0xffffffffu, a1, 16);
    a2 += __shfl_xor_sync(0xffffffffu, a2, 16);
    a3 += __shfl_xor_sync(0xffffffffu, a3, 16);
    if (half_ == 0) {
        float* dp = &agg[(size_t)dst * 64 + (cq << 2)];
        atomicAdd(dp + 0, a0);
        atomicAdd(dp + 1, a1);
        atomicAdd(dp + 2, a2);
        atomicAdd(dp + 3, a3);
    }
}

// ---------------- fused GRU: 256 thr / 32 nodes per block (2+ CTAs/SM) ----------------
__global__ void __launch_bounds__(256, 2)
k_gru_fused(const float* __restrict__ m, const float* __restrict__ wihT,
            const float* __restrict__ whhT, const float* __restrict__ bih,
            const float* __restrict__ bhh, float* __restrict__ x) {
    __shared__ float sm[32][64];
    __shared__ float sx[32][64];
    int t = threadIdx.x;
    int n0 = blockIdx.x << 5;
    for (int i = t; i < 32 * 16; i += 256) {
        int r = i >> 4, c = (i & 15) << 2;
        *(float4*)&sm[r][c] = *(const float4*)(m + (size_t)(n0 + r) * 64 + c);
        *(float4*)&sx[r][c] = *(const float4*)(x + (size_t)(n0 + r) * 64 + c);
    }
    __syncthreads();
    int o = t & 63, grp = t >> 6;   // 4 groups x 8 nodes = 32
    int nb = grp << 3;
    float a0[8] = {}, a1[8] = {}, a2[8] = {}, b0[8] = {}, b1[8] = {}, b2[8] = {};
#pragma unroll 4
    for (int k = 0; k < 64; k++) {
        float wi0 = wihT[k * 192 + o];
        float wi1 = wihT[k * 192 + 64 + o];
        float wi2 = wihT[k * 192 + 128 + o];
        float wh0 = whhT[k * 192 + o];
        float wh1 = whhT[k * 192 + 64 + o];
        float wh2 = whhT[k * 192 + 128 + o];
#pragma unroll
        for (int j = 0; j < 8; j++) {
            float mv = sm[nb + j][k];
            float xv = sx[nb + j][k];
            a0[j] += mv * wi0; a1[j] += mv * wi1; a2[j] += mv * wi2;
            b0[j] += xv * wh0; b1[j] += xv * wh1; b2[j] += xv * wh2;
        }
    }
    float bi0 = bih[o], bi1 = bih[64 + o], bi2 = bih[128 + o];
    float bh0 = bhh[o], bh1 = bhh[64 + o], bh2 = bhh[128 + o];
#pragma unroll
    for (int j = 0; j < 8; j++) {
        int n = n0 + nb + j;
        float r = sigf(a0[j] + bi0 + b0[j] + bh0);
        float z = sigf(a1[j] + bi1 + b1[j] + bh1);
        float nn = tanhf(a2[j] + bi2 + r * (b2[j] + bh2));
        float h = sx[nb + j][o];
        x[(size_t)n * 64 + o] = (1.0f - z) * nn + z * h;
    }
}

// ---------------- fused Set2Set (6 steps) + memory LSTM ----------------
__global__ void __launch_bounds__(256) k_pool(
    const float* __restrict__ x,
    const float* __restrict__ s2swihT, const float* __restrict__ s2swhhT,
    const float* __restrict__ s2s_bih, const float* __restrict__ s2s_bhh,
    const float* __restrict__ memwihT, const float* __restrict__ mem_bih,
    const float* __restrict__ mem_bhh,
    float* __restrict__ hx, float* __restrict__ out, int out_size) {
    int g = blockIdx.x, t = threadIdx.x;
    __shared__ float so[64][65];
    __shared__ float q[128], hh[64], ch[64], sgate[256], sa[64], red[64];
    for (int idx = t; idx < 4096; idx += 256) {
        int n = idx >> 6, c = idx & 63;
        so[n][c] = x[((size_t)g * 64 + n) * 64 + c];
    }
    if (t < 128) q[t] = 0.0f;
    if (t < 64) { hh[t] = 0.0f; ch[t] = 0.0f; }
    __syncthreads();
    for (int step = 0; step < 6; step++) {
        float acc = s2s_bih[t] + s2s_bhh[t];
#pragma unroll 4
        for (int j = 0; j < 128; j++) acc += q[j] * s2swihT[j * 256 + t];
#pragma unroll 4
        for (int j = 0; j < 64; j++) acc += hh[j] * s2swhhT[j * 256 + t];
        sgate[t] = acc;
        __syncthreads();
        if (t < 64) {
            float c = sigf(sgate[64 + t]) * ch[t] + sigf(sgate[t]) * tanhf(sgate[128 + t]);
            float h = sigf(sgate[192 + t]) * tanhf(c);
            ch[t] = c; hh[t] = h;
        }
        __syncthreads();
        float e = 0.0f;
        if (t < 64) {
#pragma unroll 8
            for (int c = 0; c < 64; c++) e += so[t][c] * hh[c];
            red[t] = e;
        }
        __syncthreads();
        if (t < 64) {
            float mx = -1e30f;
#pragma unroll 8
            for (int n = 0; n < 64; n++) mx = fmaxf(mx, red[n]);
            sa[t] = expf(e - mx);
        }
        __syncthreads();
        if (t < 64) {
            float ssum = 0.0f, rr = 0.0f;
#pragma unroll 8
            for (int n = 0; n < 64; n++) { ssum += sa[n]; rr += sa[n] * so[n][t]; }
            q[t] = hh[t];
            q[64 + t] = rr / ssum;
        }
        __syncthreads();
    }
    float acc = mem_bih[t] + mem_bhh[t];
#pragma unroll 4
    for (int j = 0; j < 128; j++) acc += q[j] * memwihT[j * 256 + t];
    sgate[t] = acc;
    __syncthreads();
    if (t < 64) {
        float c = sigf(sgate[t]) * tanhf(sgate[128 + t]);
        float h = sigf(sgate[192 + t]) * tanhf(c);
        hx[g * 64 + t] = h;
        int base = NT * 6;
        if (out_size >= base + 2 * NG * D) {
            out[base + g * 64 + t] = h;
            out[base + NG * 64 + g * 64 + t] = c;
        }
    }
}

// ---------------- final gather + MLP: 8 torsions per block ----------------
__global__ void __launch_bounds__(256) k_final8(
    const float* __restrict__ x, const float* __restrict__ hx,
    const int* __restrict__ nonring, const float* __restrict__ lin1T,
    const float* __restrict__ lin1b, const float* __restrict__ lin2w,
    const float* __restrict__ lin2b, float* __restrict__ out) {
    int t = threadIdx.x;
    int r0 = blockIdx.x << 3;
    __shared__ float feat[8][320];
    __shared__ float o1[8][64];
    for (int idx = t; idx < 8 * 320; idx += 256) {
        int rr = idx / 320, f = idx % 320;
        int linear = (r0 + rr) * 320 + f;
        int c = linear / (NT * 5);
        int rem = linear % (NT * 5);
        int tt = rem / 5;
        int s = rem % 5;
        float v;
        if (s == 0)
            v = hx[(tt / TPQ) * 64 + c];
        else
            v = x[(size_t)nonring[(s - 1) * NT + tt] * 64 + c];
        feat[rr][f] = v;
    }
    __syncthreads();
    int o = t & 63, tr = t >> 6;
#pragma unroll
    for (int pass = 0; pass < 2; pass++) {
        int rr = tr + (pass << 2);
        float acc = lin1b[o];
#pragma unroll 8
        for (int f = 0; f < 320; f++) acc += feat[rr][f] * lin1T[f * 64 + o];
        o1[rr][o] = fmaxf(acc, 0.0f);
    }
    __syncthreads();
    if (t < 48) {
        int rr = t / 6, a = t % 6;
        float s = lin2b[a];
#pragma unroll 8
        for (int j = 0; j < 64; j++) s += o1[rr][j] * lin2w[a * 64 + j];
        out[(r0 + rr) * 6 + a] = s;
    }
}

// ---------------- host side (launches ONLY) ----------------
extern "C" void kernel_launch(void* const* d_in, const int* in_sizes, int n_in,
                              void* d_out, int out_size) {
    const float* x_in = (const float*)d_in[0];
    const float* edge_attr = (const float*)d_in[1];
    const int* edge_index = (const int*)d_in[2];
    const int* nonring = (const int*)d_in[4];
    int wb = (n_in >= 32) ? 8 : 6;
    const float* lin0_w = (const float*)d_in[wb + 0];
    const float* lin0_b = (const float*)d_in[wb + 1];
    const float* e1_w = (const float*)d_in[wb + 2];
    const float* e1_b = (const float*)d_in[wb + 3];
    const float* e2_w = (const float*)d_in[wb + 4];
    const float* e2_b = (const float*)d_in[wb + 5];
    const float* root_w = (const float*)d_in[wb + 6];
    const float* conv_b = (const float*)d_in[wb + 7];
    const float* gru_wih = (const float*)d_in[wb + 8];
    const float* gru_whh = (const float*)d_in[wb + 9];
    const float* gru_bih = (const float*)d_in[wb + 10];
    const float* gru_bhh = (const float*)d_in[wb + 11];
    const float* s2s_wih = (const float*)d_in[wb + 12];
    const float* s2s_whh = (const float*)d_in[wb + 13];
    const float* s2s_bih = (const float*)d_in[wb + 14];
    const float* s2s_bhh = (const float*)d_in[wb + 15];
    const float* mem_wih = (const float*)d_in[wb + 16];
    const float* mem_bih = (const float*)d_in[wb + 18];
    const float* mem_bhh = (const float*)d_in[wb + 19];
    const float* lin1_w = (const float*)d_in[wb + 20];
    const float* lin1_b = (const float*)d_in[wb + 21];
    const float* lin2_w = (const float*)d_in[wb + 22];
    const float* lin2_b = (const float*)d_in[wb + 23];
    float* out = (float*)d_out;

    __half* ew;
    float *hidden, *xb, *agg, *m, *deg, *rootT, *gruWihT, *gruWhhT;
    float *s2swihT, *s2swhhT, *memwihT, *lin1T, *hx;
    cudaGetSymbolAddress((void**)&ew, g_ew);
    cudaGetSymbolAddress((void**)&hidden, g_hidden);
    cudaGetSymbolAddress((void**)&xb, g_x);
    cudaGetSymbolAddress((void**)&agg, g_agg);
    cudaGetSymbolAddress((void**)&m, g_m);
    cudaGetSymbolAddress((void**)&deg, g_deg);
    cudaGetSymbolAddress((void**)&rootT, g_rootT);
    cudaGetSymbolAddress((void**)&gruWihT, g_gru_wihT);
    cudaGetSymbolAddress((void**)&gruWhhT, g_gru_whhT);
    cudaGetSymbolAddress((void**)&s2swihT, g_s2s_wihT);
    cudaGetSymbolAddress((void**)&s2swhhT, g_s2s_whhT);
    cudaGetSymbolAddress((void**)&memwihT, g_mem_wihT);
    cudaGetSymbolAddress((void**)&lin1T, g_lin1T);
    cudaGetSymbolAddress((void**)&hx, g_hx);

    // 1: edge hidden
    k_hidden<<<(NE * D + 255) / 256, 256>>>(edge_attr, e1_w, e1_b, hidden);
    // 2: node projection + zero agg/deg
    k_lin0z<<<(NNODES * D + 255) / 256, 256>>>(x_in, lin0_w, lin0_b, xb, agg, deg);
    // 3: degree histogram
    k_deg<<<(NE + 255) / 256, 256>>>(edge_index, deg);
    // 4: ew GEMM (fp16x2 error-compensated) — profiled slot
    k_ew_fp16x2<<<dim3(4096 / 64, NE / 128), 256>>>(hidden, e2_w, e2_b, ew);
    // 5-6: weight transposes
    k_transpose<<<(64 * 64 + 255) / 256, 256>>>(root_w, rootT, 64, 64);
    k_prep<<<(126976 + 255) / 256, 256>>>(gru_wih, gru_whh, s2s_wih, s2s_whh, mem_wih,
                                          lin1_w, gruWihT, gruWhhT, s2swihT, s2swhhT,
                                          memwihT, lin1T);

    // 6 NNConv + GRU iterations (gemm64 epilogue zeroes agg for the next msg)
    for (int it = 0; it < 6; it++) {
        k_msg<<<NE / 8, 256>>>(xb, edge_index, ew, agg);
        k_gemm64<<<dim3(1, NNODES / 64), 256>>>(xb, rootT, conv_b, m, 64, 1, agg, deg);
        k_gru_fused<<<512, 256>>>(m, gruWihT, gruWhhT, gru_bih, gru_bhh, xb);
    }

    // fused Set2Set + memory LSTM, then final gather + MLP
    k_pool<<<NG, 256>>>(xb, s2swihT, s2swhhT, s2s_bih, s2s_bhh, memwihT, mem_bih,
                        mem_bhh, hx, out, out_size);
    k_final8<<<NT / 8, 256>>>(xb, hx, nonring, lin1T, lin1_b, lin2_w, lin2_b, out);
}